// round 11
// baseline (speedup 1.0000x reference)
#include <cuda_runtime.h>
#include <cuda_bf16.h>
#include <cstdint>

#define LEAK 0.5f
typedef __nv_bfloat16 bf16;

// ---------------------------------------------------------------------------
// Global scratch (allocation-free). Channel-chunked bf16 layouts:
//   act buffers: [n][chunk=ci/16][y][x][16ci]   (hi and lo parts)
// Weights: fragment-vector layout [tap][chunk][co][j], j in [0,16):
//   tq=j/4, r=j%4 -> k_in_chunk = 2*tq + (r&1) + (r>>1)*8
// so each mma thread's (b0,b1) is one contiguous 8-byte LDG.64.
// ---------------------------------------------------------------------------
__device__ bf16  g_b1h[32 * 8 * 111 * 111 * 16]; // conv1 out hi (101 MB)
__device__ bf16  g_b1l[32 * 8 * 111 * 111 * 16]; // conv1 out lo
__device__ bf16  g_b2h[32 * 4 * 54 * 54 * 16];   // conv2 out hi (12 MB)
__device__ bf16  g_b2l[32 * 4 * 54 * 54 * 16];   // conv2 out lo
__device__ float g_buf3[32 * 32 * 26 * 26];      // conv3 out fp32 NCHW
__device__ bf16  g_w2f[9 * 8 * 64 * 16];         // w2 binarized, frag-vec layout
__device__ bf16  g_w3f[9 * 4 * 32 * 16];         // w3 binarized, frag-vec layout
__device__ bf16  g_w1f[128 * 16];                // w1 binarized, frag-vec (K=taps)

// ---------------------------------------------------------------------------
// One-time weight binarization into frag-vector layouts.
// w2/w3: [tap][chunk][co][j] (j -> k_in_chunk).  w1: [co][j] (j -> tap, pad 0).
// ---------------------------------------------------------------------------
__global__ __launch_bounds__(256)
void k_prep(const float* __restrict__ w2, const float* __restrict__ w3,
            const float* __restrict__ w1)
{
    int i = blockIdx.x * 256 + threadIdx.x;
    if (i < 9 * 8 * 64 * 16) {
        int j = i & 15, co = (i >> 4) & 63;
        int rest = i >> 10, ch = rest & 7, tap = rest >> 3;
        int tq = j >> 2, r = j & 3;
        int k = 2 * tq + (r & 1) + ((r >> 1) << 3);
        float v = w2[((size_t)co * 128 + ch * 16 + k) * 9 + tap];
        g_w2f[i] = __float2bfloat16((v >= 0.f) ? 1.f : -1.f);
    } else if (i < 9 * 8 * 64 * 16 + 9 * 4 * 32 * 16) {
        int jj = i - 9 * 8 * 64 * 16;
        int j = jj & 15, co = (jj >> 4) & 31;
        int rest = jj >> 9, ch = rest & 3, tap = rest >> 2;
        int tq = j >> 2, r = j & 3;
        int k = 2 * tq + (r & 1) + ((r >> 1) << 3);
        float v = w3[((size_t)co * 64 + ch * 16 + k) * 9 + tap];
        g_w3f[jj] = __float2bfloat16((v >= 0.f) ? 1.f : -1.f);
    } else if (i < 9 * 8 * 64 * 16 + 9 * 4 * 32 * 16 + 128 * 16) {
        int jj = i - (9 * 8 * 64 * 16 + 9 * 4 * 32 * 16);
        int j = jj & 15, co = jj >> 4;
        int tq = j >> 2, r = j & 3;
        int k = 2 * tq + (r & 1) + ((r >> 1) << 3);   // tap index 0..15
        float s = 0.f;
        if (k < 9) s = (w1[co * 9 + k] >= 0.f) ? 1.f : -1.f;
        g_w1f[jj] = __float2bfloat16(s);
    }
}

// ---------------------------------------------------------------------------
// mma.sync m16n8k16 bf16 -> fp32 ; cp.async helpers
// ---------------------------------------------------------------------------
__device__ __forceinline__ void mma_bf16(float* d,
                                         unsigned a0, unsigned a1,
                                         unsigned a2, unsigned a3,
                                         unsigned b0, unsigned b1)
{
    asm volatile(
        "mma.sync.aligned.m16n8k16.row.col.f32.bf16.bf16.f32 "
        "{%0,%1,%2,%3}, {%4,%5,%6,%7}, {%8,%9}, {%0,%1,%2,%3};\n"
        : "+f"(d[0]), "+f"(d[1]), "+f"(d[2]), "+f"(d[3])
        : "r"(a0), "r"(a1), "r"(a2), "r"(a3), "r"(b0), "r"(b1));
}

__device__ __forceinline__ void cp16(void* dst, const void* src, bool p)
{
    unsigned d = (unsigned)__cvta_generic_to_shared(dst);
    asm volatile("cp.async.cg.shared.global [%0], [%1], 16, %2;"
                 :: "r"(d), "l"(src), "r"(p ? 16u : 0u));
}
__device__ __forceinline__ void cp_commit() {
    asm volatile("cp.async.commit_group;");
}
template<int N>
__device__ __forceinline__ void cp_wait() {
    asm volatile("cp.async.wait_group %0;" :: "n"(N));
}

__device__ __forceinline__ unsigned pk_bf2(bf16 lo, bf16 hi)
{
    unsigned short a = *(unsigned short*)&lo;
    unsigned short b = *(unsigned short*)&hi;
    return (unsigned)a | ((unsigned)b << 16);
}

// ---------------------------------------------------------------------------
// Stage 1 on tensor cores: conv(1->128,3x3)+bias+leaky+maxpool2.
// GEMM: M = 128 conv positions (8 rows x 16 cols -> pooled 4x8),
// N = 64 co (grid.y half), K = 16 (9 taps + 7 zero pad). x split bf16 hi/lo.
// A fragments gathered from a 10x18 staged x tile; B frags via LDG.64.
// Emits bf16 hi/lo chunk-last [n][cg][y][x][16].
// ---------------------------------------------------------------------------
__global__ __launch_bounds__(128)
void k_conv1_mma(const float* __restrict__ x, const bf16* __restrict__ w1f,
                 const float* __restrict__ b1,
                 bf16* __restrict__ outh, bf16* __restrict__ outl)
{
    extern __shared__ __align__(16) char smem_raw[];
    bf16* xh = (bf16*)smem_raw;          // [10][20]
    bf16* xl = xh + 200;                 // [10][20]

    const int n   = blockIdx.z;
    const int co0 = blockIdx.y * 64;
    const int ty  = blockIdx.x / 14, tx = blockIdx.x % 14;
    const int ph0 = ty * 4, pw0 = tx * 8;
    const int ih0 = 2 * ph0, iw0 = 2 * pw0;
    const int t    = threadIdx.x;
    const int lane = t & 31, wm = t >> 5;
    const int g    = lane >> 2, tig = lane & 3;

    const float* xn = x + (size_t)n * 224 * 224;
    for (int i = t; i < 180; i += 128) {
        int r = i / 18, c = i % 18;
        int ir = ih0 + r, ic = iw0 + c;
        float v = (ir < 224 && ic < 224) ? xn[ir * 224 + ic] : 0.f;
        bf16 h = __float2bfloat16(v);
        xh[r * 20 + c] = h;
        xl[r * 20 + c] = __float2bfloat16(v - __bfloat162float(h));
    }
    __syncthreads();

    // B fragments (one LDG.64 per n8 tile)
    unsigned b0[8], b1r[8];
#pragma unroll
    for (int nt = 0; nt < 8; nt++) {
        const bf16* wp = w1f + ((size_t)(co0 + nt * 8 + g)) * 16 + tig * 4;
        uint2 bv = *(const uint2*)wp;
        b0[nt] = bv.x;
        b1r[nt] = bv.y;
    }

    float acc[2][8][4];
#pragma unroll
    for (int mt = 0; mt < 2; mt++)
#pragma unroll
        for (int nt = 0; nt < 8; nt++)
#pragma unroll
            for (int j = 0; j < 4; j++) acc[mt][nt][j] = 0.f;

    // gather helper: A[m=(my,mx)][k=tap]; taps >= 9 are zero
    auto gx = [&](const bf16* s, int my, int mx, int k) -> bf16 {
        if (k >= 9) return __float2bfloat16(0.f);
        int kh = k / 3, kw = k - kh * 3;
        return s[(my + kh) * 20 + (mx + kw)];
    };

#pragma unroll
    for (int mt = 0; mt < 2; mt++) {
        const int my = 2 * wm + mt;
        unsigned ah[4], al[4];
        ah[0] = pk_bf2(gx(xh, my, g,     2 * tig),     gx(xh, my, g,     2 * tig + 1));
        ah[1] = pk_bf2(gx(xh, my, g + 8, 2 * tig),     gx(xh, my, g + 8, 2 * tig + 1));
        ah[2] = pk_bf2(gx(xh, my, g,     2 * tig + 8), gx(xh, my, g,     2 * tig + 9));
        ah[3] = pk_bf2(gx(xh, my, g + 8, 2 * tig + 8), gx(xh, my, g + 8, 2 * tig + 9));
        al[0] = pk_bf2(gx(xl, my, g,     2 * tig),     gx(xl, my, g,     2 * tig + 1));
        al[1] = pk_bf2(gx(xl, my, g + 8, 2 * tig),     gx(xl, my, g + 8, 2 * tig + 1));
        al[2] = pk_bf2(gx(xl, my, g,     2 * tig + 8), gx(xl, my, g,     2 * tig + 9));
        al[3] = pk_bf2(gx(xl, my, g + 8, 2 * tig + 8), gx(xl, my, g + 8, 2 * tig + 9));
#pragma unroll
        for (int nt = 0; nt < 8; nt++) {
            mma_bf16(acc[mt][nt], ah[0], ah[1], ah[2], ah[3], b0[nt], b1r[nt]);
            mma_bf16(acc[mt][nt], al[0], al[1], al[2], al[3], b0[nt], b1r[nt]);
        }
    }
    __syncthreads();

    // epilogue: frags -> smem (overlay), then pool+bias+leaky -> hi/lo out
    float* sd = (float*)smem_raw;         // [128][68]
    const int SD = 68;
#pragma unroll
    for (int mt = 0; mt < 2; mt++) {
        int m0 = wm * 32 + mt * 16 + g;
#pragma unroll
        for (int nt = 0; nt < 8; nt++) {
            int n0 = nt * 8 + 2 * tig;
            *(float2*)&sd[m0 * SD + n0] = make_float2(acc[mt][nt][0], acc[mt][nt][1]);
            *(float2*)&sd[(m0 + 8) * SD + n0] = make_float2(acc[mt][nt][2], acc[mt][nt][3]);
        }
    }
    __syncthreads();

    {
        int pp = t >> 2, cq = t & 3;      // 32 px x 4 chunks
        int py = pp >> 3, px = pp & 7;
        int ph = ph0 + py, pw = pw0 + px;
        if (ph < 111 && pw < 111) {
            int mA = (2 * py) * 16 + 2 * px;
            bf16 oh[16], ol[16];
#pragma unroll
            for (int j = 0; j < 16; j++) {
                int col = cq * 16 + j;
                float v0 = sd[mA * SD + col];
                float v1 = sd[(mA + 1) * SD + col];
                float v2 = sd[(mA + 16) * SD + col];
                float v3 = sd[(mA + 17) * SD + col];
                float m = fmaxf(fmaxf(v0, v1), fmaxf(v2, v3));
                m += __ldg(&b1[co0 + col]);
                m = (m >= 0.f) ? m : LEAK * m;
                bf16 hh = __float2bfloat16(m);
                oh[j] = hh;
                ol[j] = __float2bfloat16(m - __bfloat162float(hh));
            }
            int chunkg = blockIdx.y * 4 + cq;
            size_t gi = ((((size_t)n * 8 + chunkg) * 111 + ph) * 111 + pw) * 16;
            *(uint4*)&outh[gi]     = *(const uint4*)&oh[0];
            *(uint4*)&outh[gi + 8] = *(const uint4*)&oh[8];
            *(uint4*)&outl[gi]     = *(const uint4*)&ol[0];
            *(uint4*)&outl[gi + 8] = *(const uint4*)&ol[8];
        }
    }
}

// ---------------------------------------------------------------------------
// Stages 2/3, tensor cores. Implicit GEMM: block M = 256 conv positions
// (16 rows x 16 cols -> pooled 8x8), N = CO. 8 warps, ALL in M:
// warp tile M32 x N=CO. K = tap-loop x 16-ci chunks; bf16 hi+lo split.
// Triple-buffered cp.async staging, one barrier per chunk. B frags: one
// LDG.64 per n8-tile. OUTF=1: bf16 hi/lo chunk-last; OUTF=0: fp32 NCHW.
// ---------------------------------------------------------------------------
template<int CI, int CO, int HIN, int POUT, int OUTF>
__global__ __launch_bounds__(256)
void k_conv_mma(const bf16* __restrict__ inh, const bf16* __restrict__ inl,
                const bf16* __restrict__ wf,  const float* __restrict__ bg,
                bf16* __restrict__ outh, bf16* __restrict__ outl,
                float* __restrict__ outf)
{
    constexpr int NCH   = CI / 16;
    constexpr int NCHO  = CO / 16;
    constexpr int NT    = CO / 8;        // n8 tiles per warp (8 or 4)
    constexpr int NTX   = (POUT + 7) / 8;
    constexpr int SD    = CO + 4;
    constexpr int SLOT  = 24;            // ci-slot stride (conflict-free)
    constexpr int POS   = 18 * 18;       // tile positions incl. halo
    constexpr int SX_E  = POS * SLOT;    // elems per (buf, part)
    constexpr int BUF_E = 2 * SX_E;      // hi + lo

    extern __shared__ __align__(16) char smem_raw[];
    bf16* sbuf = (bf16*)smem_raw;        // 3 x BUF_E

    const int n   = blockIdx.z;
    const int ty  = blockIdx.x / NTX, tx = blockIdx.x % NTX;
    const int ph0 = ty * 8, pw0 = tx * 8;
    const int ih0 = 2 * ph0, iw0 = 2 * pw0;

    const int t    = threadIdx.x;
    const int lane = t & 31, wm = t >> 5;   // 8 warps, all in M
    const int g    = lane >> 2, tig = lane & 3;

    float acc[2][NT][4];
#pragma unroll
    for (int mt = 0; mt < 2; mt++)
#pragma unroll
        for (int nt = 0; nt < NT; nt++)
#pragma unroll
            for (int j = 0; j < 4; j++) acc[mt][nt][j] = 0.f;

    int abase[2];
#pragma unroll
    for (int mt = 0; mt < 2; mt++)
        abase[mt] = (((2 * wm + mt) * 18) + g) * SLOT + 2 * tig;

    // staging issue: chunk ch -> buffer b (cp.async, zfill halo)
    auto stage = [&](int ch, int b) {
        const bf16* srch = inh + ((size_t)(n * NCH + ch) * HIN * HIN) * 16;
        const bf16* srcl = inl + ((size_t)(n * NCH + ch) * HIN * HIN) * 16;
        bf16* dh = sbuf + b * BUF_E;
        bf16* dl = dh + SX_E;
        for (int u = t; u < POS * 2; u += 256) {
            int pos = u >> 1, h4 = u & 1;
            int r = pos / 18, c = pos - r * 18;
            int ir = ih0 + r, ic = iw0 + c;
            bool p = (ir < HIN) && (ic < HIN);
            size_t gi = ((size_t)ir * HIN + ic) * 16 + h4 * 8;
            int si = pos * SLOT + h4 * 8;
            cp16(dh + si, srch + gi, p);
            cp16(dl + si, srcl + gi, p);
        }
    };

    stage(0, 0);
    cp_commit();
    if (NCH > 1) { stage(1, 1); cp_commit(); }

    for (int ch = 0; ch < NCH; ch++) {
        if (ch + 1 < NCH) cp_wait<1>(); else cp_wait<0>();
        __syncthreads();

        if (ch + 2 < NCH) { stage(ch + 2, (ch + 2) % 3); cp_commit(); }

        const bf16* sx_hi = sbuf + (ch % 3) * BUF_E;
        const bf16* sx_lo = sx_hi + SX_E;
        const bf16* wfc   = wf + ((size_t)ch * CO) * 16;

#pragma unroll
        for (int kh = 0; kh < 3; kh++)
#pragma unroll
            for (int kw = 0; kw < 3; kw++) {
                const int tap  = kh * 3 + kw;
                const int toff = (kh * 18 + kw) * SLOT;

                unsigned b0[NT], b1[NT];
#pragma unroll
                for (int nt = 0; nt < NT; nt++) {
                    const bf16* wp = wfc + ((size_t)tap * NCH * CO +
                                            nt * 8 + g) * 16 + tig * 4;
                    uint2 bv = *(const uint2*)wp;
                    b0[nt] = bv.x;
                    b1[nt] = bv.y;
                }

#pragma unroll
                for (int mt = 0; mt < 2; mt++) {
                    int ai = abase[mt] + toff;
                    unsigned ah0 = *(const unsigned*)&sx_hi[ai];
                    unsigned ah2 = *(const unsigned*)&sx_hi[ai + 8];
                    unsigned ah1 = *(const unsigned*)&sx_hi[ai + 8 * SLOT];
                    unsigned ah3 = *(const unsigned*)&sx_hi[ai + 8 * SLOT + 8];
                    unsigned al0 = *(const unsigned*)&sx_lo[ai];
                    unsigned al2 = *(const unsigned*)&sx_lo[ai + 8];
                    unsigned al1 = *(const unsigned*)&sx_lo[ai + 8 * SLOT];
                    unsigned al3 = *(const unsigned*)&sx_lo[ai + 8 * SLOT + 8];
#pragma unroll
                    for (int nt = 0; nt < NT; nt++) {
                        mma_bf16(acc[mt][nt], ah0, ah1, ah2, ah3, b0[nt], b1[nt]);
                        mma_bf16(acc[mt][nt], al0, al1, al2, al3, b0[nt], b1[nt]);
                    }
                }
            }
    }
    __syncthreads();

    // ---- epilogue: fragments -> smem (overlay) ----
    float* sd = (float*)smem_raw;
#pragma unroll
    for (int mt = 0; mt < 2; mt++) {
        int m0 = wm * 32 + mt * 16 + g;
#pragma unroll
        for (int nt = 0; nt < NT; nt++) {
            int n0 = nt * 8 + 2 * tig;
            *(float2*)&sd[m0 * SD + n0] =
                make_float2(acc[mt][nt][0], acc[mt][nt][1]);
            *(float2*)&sd[(m0 + 8) * SD + n0] =
                make_float2(acc[mt][nt][2], acc[mt][nt][3]);
        }
    }
    __syncthreads();

    // ---- fused maxpool(2x2) + bias + leaky ----
    if (OUTF == 1) {
        // 64 pooled px x 4 chunks = 256 threads; 16 co each (NCHO==4)
        int pp = t >> 2, chunk = t & 3;
        int py = pp >> 3, px = pp & 7;
        int ph = ph0 + py, pw = pw0 + px;
        if (ph < POUT && pw < POUT) {
            int mA = (2 * py) * 16 + 2 * px;
            bf16 oh[16], ol[16];
#pragma unroll
            for (int j = 0; j < 16; j++) {
                int co = chunk * 16 + j;
                float v0 = sd[mA * SD + co];
                float v1 = sd[(mA + 1) * SD + co];
                float v2 = sd[(mA + 16) * SD + co];
                float v3 = sd[(mA + 17) * SD + co];
                float m = fmaxf(fmaxf(v0, v1), fmaxf(v2, v3));
                m += __ldg(&bg[co]);
                m = (m >= 0.f) ? m : LEAK * m;
                bf16 hh = __float2bfloat16(m);
                oh[j] = hh;
                ol[j] = __float2bfloat16(m - __bfloat162float(hh));
            }
            size_t gi = ((((size_t)n * NCHO + chunk) * POUT + ph) * POUT + pw) * 16;
            *(uint4*)&outh[gi]     = *(const uint4*)&oh[0];
            *(uint4*)&outh[gi + 8] = *(const uint4*)&oh[8];
            *(uint4*)&outl[gi]     = *(const uint4*)&ol[0];
            *(uint4*)&outl[gi + 8] = *(const uint4*)&ol[8];
        }
    } else {
        // fp32 NCHW output (feeds scalar conv4): 64 px x 4 co-groups of 8
        int pp = t >> 2, cq = t & 3;
        int py = pp >> 3, px = pp & 7;
        int ph = ph0 + py, pw = pw0 + px;
        if (ph < POUT && pw < POUT) {
            int mA = (2 * py) * 16 + 2 * px;
#pragma unroll
            for (int j = 0; j < 8; j++) {
                int co = cq * 8 + j;
                float v0 = sd[mA * SD + co];
                float v1 = sd[(mA + 1) * SD + co];
                float v2 = sd[(mA + 16) * SD + co];
                float v3 = sd[(mA + 17) * SD + co];
                float m = fmaxf(fmaxf(v0, v1), fmaxf(v2, v3));
                m += __ldg(&bg[co]);
                m = (m >= 0.f) ? m : LEAK * m;
                outf[(((size_t)n * CO + co) * POUT + ph) * POUT + pw] = m;
            }
        }
    }
}

// ---------------------------------------------------------------------------
// Stage 4: conv(32->8, kh=3 kw=2) + bias, no pool.
// ---------------------------------------------------------------------------
__global__ __launch_bounds__(256)
void k_conv4(const float* __restrict__ w4, const float* __restrict__ b4,
             float* __restrict__ out)
{
    __shared__ float sw[8][32][3][2];
    __shared__ float sb[8];
    const int t = threadIdx.x;
    for (int i = t; i < 8 * 32 * 6; i += 256)
        ((float*)sw)[i] = (w4[i] >= 0.f) ? 1.f : -1.f;
    if (t < 8) sb[t] = b4[t];
    __syncthreads();

    int idx = blockIdx.x * 256 + t;
    if (idx >= 32 * 8 * 24 * 25) return;
    int ow = idx % 25; int r = idx / 25;
    int oh = r % 24;   r /= 24;
    int co = r % 8;    int n = r / 8;

    const float* xn = g_buf3 + ((size_t)n * 32) * (26 * 26);
    float a = sb[co];
#pragma unroll 4
    for (int ci = 0; ci < 32; ci++) {
        const float* xr = xn + ci * 676 + oh * 26 + ow;
#pragma unroll
        for (int kh = 0; kh < 3; kh++)
#pragma unroll
            for (int kw = 0; kw < 2; kw++)
                a += sw[co][ci][kh][kw] * __ldg(&xr[kh * 26 + kw]);
    }
    out[idx] = a;
}

// ---------------------------------------------------------------------------
extern "C" void kernel_launch(void* const* d_in, const int* in_sizes, int n_in,
                              void* d_out, int out_size)
{
    (void)in_sizes; (void)n_in; (void)out_size;
    const float* x  = (const float*)d_in[0];
    const float* w1 = (const float*)d_in[1];
    const float* b1 = (const float*)d_in[2];
    const float* w2 = (const float*)d_in[3];
    const float* b2 = (const float*)d_in[4];
    const float* w3 = (const float*)d_in[5];
    const float* b3 = (const float*)d_in[6];
    const float* w4 = (const float*)d_in[7];
    const float* b4 = (const float*)d_in[8];
    float* out = (float*)d_out;

    bf16 *b1h, *b1l, *b2h, *b2l, *w2f, *w3f, *w1f;
    float* buf3;
    cudaGetSymbolAddress((void**)&b1h, g_b1h);
    cudaGetSymbolAddress((void**)&b1l, g_b1l);
    cudaGetSymbolAddress((void**)&b2h, g_b2h);
    cudaGetSymbolAddress((void**)&b2l, g_b2l);
    cudaGetSymbolAddress((void**)&w2f, g_w2f);
    cudaGetSymbolAddress((void**)&w3f, g_w3f);
    cudaGetSymbolAddress((void**)&w1f, g_w1f);
    cudaGetSymbolAddress((void**)&buf3, g_buf3);

    // smem: 3 staging buffers 3*2*(324*24)*2B = 93312 (> epilogue 69632)
    const int smem23 = 3 * 2 * (18 * 18 * 24) * 2;  // 93312
    cudaFuncSetAttribute(k_conv_mma<128, 64, 111, 54, 1>,
                         cudaFuncAttributeMaxDynamicSharedMemorySize, smem23);
    cudaFuncSetAttribute(k_conv_mma<64, 32, 54, 26, 0>,
                         cudaFuncAttributeMaxDynamicSharedMemorySize, smem23);
    const int smem1 = 128 * 68 * 4;                  // 34816 (epilogue dominates)

    k_prep<<<dim3(368), 256>>>(w2, w3, w1);

    // conv1 (tensor): pooled 111 -> y tiles 28 (x4), x tiles 14 (x8); 2 co halves
    k_conv1_mma<<<dim3(28 * 14, 2, 32), 128, smem1>>>(x, w1f, b1, b1h, b1l);

    // conv2: POUT=54 -> 7x7 tiles of pooled 8x8
    k_conv_mma<128, 64, 111, 54, 1><<<dim3(7 * 7, 1, 32), 256, smem23>>>(
        b1h, b1l, w2f, b2, b2h, b2l, nullptr);

    // conv3: POUT=26 -> 4x4 tiles
    k_conv_mma<64, 32, 54, 26, 0><<<dim3(4 * 4, 1, 32), 256, smem23>>>(
        b2h, b2l, w3f, b3, nullptr, nullptr, buf3);

    k_conv4<<<dim3((32 * 8 * 24 * 25 + 255) / 256), 256>>>(w4, b4, out);
}

// round 12
// speedup vs baseline: 1.1556x; 1.1556x over previous
#include <cuda_runtime.h>
#include <cuda_bf16.h>
#include <cstdint>

#define LEAK 0.5f
typedef __nv_bfloat16 bf16;

// ---------------------------------------------------------------------------
// Global scratch (allocation-free). Channel-chunked bf16 layouts:
//   act buffers: [n][chunk=ci/16][y][x][16ci]   (hi and lo parts)
// Weights: fragment-vector layout [tap][chunk][co][j], j in [0,16):
//   tq=j/4, r=j%4 -> k_in_chunk = 2*tq + (r&1) + (r>>1)*8
// so each mma thread's (b0,b1) is one contiguous 8-byte LDG.64.
// ---------------------------------------------------------------------------
__device__ bf16  g_b1h[32 * 8 * 111 * 111 * 16]; // conv1 out hi (101 MB)
__device__ bf16  g_b1l[32 * 8 * 111 * 111 * 16]; // conv1 out lo
__device__ bf16  g_b2h[32 * 4 * 54 * 54 * 16];   // conv2 out hi (12 MB)
__device__ bf16  g_b2l[32 * 4 * 54 * 54 * 16];   // conv2 out lo
__device__ float g_buf3[32 * 32 * 26 * 26];      // conv3 out fp32 NCHW
__device__ bf16  g_w2f[9 * 8 * 64 * 16];         // w2 binarized, frag-vec layout
__device__ bf16  g_w3f[9 * 4 * 32 * 16];         // w3 binarized, frag-vec layout
__device__ bf16  g_w1f[128 * 16];                // w1 binarized, frag-vec (K=taps)

// ---------------------------------------------------------------------------
// One-time weight binarization into frag-vector layouts.
// ---------------------------------------------------------------------------
__global__ __launch_bounds__(256)
void k_prep(const float* __restrict__ w2, const float* __restrict__ w3,
            const float* __restrict__ w1)
{
    int i = blockIdx.x * 256 + threadIdx.x;
    if (i < 9 * 8 * 64 * 16) {
        int j = i & 15, co = (i >> 4) & 63;
        int rest = i >> 10, ch = rest & 7, tap = rest >> 3;
        int tq = j >> 2, r = j & 3;
        int k = 2 * tq + (r & 1) + ((r >> 1) << 3);
        float v = w2[((size_t)co * 128 + ch * 16 + k) * 9 + tap];
        g_w2f[i] = __float2bfloat16((v >= 0.f) ? 1.f : -1.f);
    } else if (i < 9 * 8 * 64 * 16 + 9 * 4 * 32 * 16) {
        int jj = i - 9 * 8 * 64 * 16;
        int j = jj & 15, co = (jj >> 4) & 31;
        int rest = jj >> 9, ch = rest & 3, tap = rest >> 2;
        int tq = j >> 2, r = j & 3;
        int k = 2 * tq + (r & 1) + ((r >> 1) << 3);
        float v = w3[((size_t)co * 64 + ch * 16 + k) * 9 + tap];
        g_w3f[jj] = __float2bfloat16((v >= 0.f) ? 1.f : -1.f);
    } else if (i < 9 * 8 * 64 * 16 + 9 * 4 * 32 * 16 + 128 * 16) {
        int jj = i - (9 * 8 * 64 * 16 + 9 * 4 * 32 * 16);
        int j = jj & 15, co = jj >> 4;
        int tq = j >> 2, r = j & 3;
        int k = 2 * tq + (r & 1) + ((r >> 1) << 3);   // tap index 0..15
        float s = 0.f;
        if (k < 9) s = (w1[co * 9 + k] >= 0.f) ? 1.f : -1.f;
        g_w1f[jj] = __float2bfloat16(s);
    }
}

// ---------------------------------------------------------------------------
// mma.sync m16n8k16 bf16 -> fp32 ; cp.async helpers
// ---------------------------------------------------------------------------
__device__ __forceinline__ void mma_bf16(float* d,
                                         unsigned a0, unsigned a1,
                                         unsigned a2, unsigned a3,
                                         unsigned b0, unsigned b1)
{
    asm volatile(
        "mma.sync.aligned.m16n8k16.row.col.f32.bf16.bf16.f32 "
        "{%0,%1,%2,%3}, {%4,%5,%6,%7}, {%8,%9}, {%0,%1,%2,%3};\n"
        : "+f"(d[0]), "+f"(d[1]), "+f"(d[2]), "+f"(d[3])
        : "r"(a0), "r"(a1), "r"(a2), "r"(a3), "r"(b0), "r"(b1));
}

__device__ __forceinline__ void cp16(void* dst, const void* src, bool p)
{
    unsigned d = (unsigned)__cvta_generic_to_shared(dst);
    asm volatile("cp.async.cg.shared.global [%0], [%1], 16, %2;"
                 :: "r"(d), "l"(src), "r"(p ? 16u : 0u));
}
__device__ __forceinline__ void cp_commit() {
    asm volatile("cp.async.commit_group;");
}
template<int N>
__device__ __forceinline__ void cp_wait() {
    asm volatile("cp.async.wait_group %0;" :: "n"(N));
}

__device__ __forceinline__ unsigned pk_bf2(bf16 lo, bf16 hi)
{
    unsigned short a = *(unsigned short*)&lo;
    unsigned short b = *(unsigned short*)&hi;
    return (unsigned)a | ((unsigned)b << 16);
}

// ---------------------------------------------------------------------------
// Stage 1 on tensor cores: conv(1->128,3x3)+bias+leaky+maxpool2.
// Block M = 256 conv positions (16 rows x 16 cols -> pooled 8x8), 8 warps
// all in M, N = 64 co (grid.y selects half). K = 16 (9 taps + 7 zero pad),
// x split bf16 hi/lo. A frags gathered from an 18x18 staged x tile.
// Emits bf16 hi/lo chunk-last [n][cg][y][x][16].
// ---------------------------------------------------------------------------
__global__ __launch_bounds__(256)
void k_conv1_mma(const float* __restrict__ x, const bf16* __restrict__ w1f,
                 const float* __restrict__ b1,
                 bf16* __restrict__ outh, bf16* __restrict__ outl)
{
    extern __shared__ __align__(16) char smem_raw[];
    bf16* xh = (bf16*)smem_raw;          // [18][20]
    bf16* xl = xh + 360;                 // [18][20]

    const int n   = blockIdx.z;
    const int co0 = blockIdx.y * 64;
    const int ty  = blockIdx.x / 14, tx = blockIdx.x % 14;
    const int ph0 = ty * 8, pw0 = tx * 8;
    const int ih0 = 2 * ph0, iw0 = 2 * pw0;
    const int t    = threadIdx.x;
    const int lane = t & 31, wm = t >> 5;   // 8 warps, all in M
    const int g    = lane >> 2, tig = lane & 3;

    const float* xn = x + (size_t)n * 224 * 224;
    for (int i = t; i < 324; i += 256) {
        int r = i / 18, c = i % 18;
        int ir = ih0 + r, ic = iw0 + c;
        float v = (ir < 224 && ic < 224) ? xn[ir * 224 + ic] : 0.f;
        bf16 h = __float2bfloat16(v);
        xh[r * 20 + c] = h;
        xl[r * 20 + c] = __float2bfloat16(v - __bfloat162float(h));
    }
    __syncthreads();

    // B fragments (one LDG.64 per n8 tile)
    unsigned b0[8], b1r[8];
#pragma unroll
    for (int nt = 0; nt < 8; nt++) {
        const bf16* wp = w1f + ((size_t)(co0 + nt * 8 + g)) * 16 + tig * 4;
        uint2 bv = *(const uint2*)wp;
        b0[nt] = bv.x;
        b1r[nt] = bv.y;
    }

    float acc[2][8][4];
#pragma unroll
    for (int mt = 0; mt < 2; mt++)
#pragma unroll
        for (int nt = 0; nt < 8; nt++)
#pragma unroll
            for (int j = 0; j < 4; j++) acc[mt][nt][j] = 0.f;

    // gather helper: A[m=(my,mx)][k=tap]; taps >= 9 are zero
    auto gx = [&](const bf16* s, int my, int mx, int k) -> bf16 {
        if (k >= 9) return __float2bfloat16(0.f);
        int kh = k / 3, kw = k - kh * 3;
        return s[(my + kh) * 20 + (mx + kw)];
    };

#pragma unroll
    for (int mt = 0; mt < 2; mt++) {
        const int my = 2 * wm + mt;     // 0..15
        unsigned ah[4], al[4];
        ah[0] = pk_bf2(gx(xh, my, g,     2 * tig),     gx(xh, my, g,     2 * tig + 1));
        ah[1] = pk_bf2(gx(xh, my, g + 8, 2 * tig),     gx(xh, my, g + 8, 2 * tig + 1));
        ah[2] = pk_bf2(gx(xh, my, g,     2 * tig + 8), gx(xh, my, g,     2 * tig + 9));
        ah[3] = pk_bf2(gx(xh, my, g + 8, 2 * tig + 8), gx(xh, my, g + 8, 2 * tig + 9));
        al[0] = pk_bf2(gx(xl, my, g,     2 * tig),     gx(xl, my, g,     2 * tig + 1));
        al[1] = pk_bf2(gx(xl, my, g + 8, 2 * tig),     gx(xl, my, g + 8, 2 * tig + 1));
        al[2] = pk_bf2(gx(xl, my, g,     2 * tig + 8), gx(xl, my, g,     2 * tig + 9));
        al[3] = pk_bf2(gx(xl, my, g + 8, 2 * tig + 8), gx(xl, my, g + 8, 2 * tig + 9));
#pragma unroll
        for (int nt = 0; nt < 8; nt++) {
            mma_bf16(acc[mt][nt], ah[0], ah[1], ah[2], ah[3], b0[nt], b1r[nt]);
            mma_bf16(acc[mt][nt], al[0], al[1], al[2], al[3], b0[nt], b1r[nt]);
        }
    }
    __syncthreads();

    // epilogue: frags -> smem (overlay), then pool+bias+leaky -> hi/lo out
    float* sd = (float*)smem_raw;         // [256][68]
    const int SD = 68;
#pragma unroll
    for (int mt = 0; mt < 2; mt++) {
        int m0 = wm * 32 + mt * 16 + g;
#pragma unroll
        for (int nt = 0; nt < 8; nt++) {
            int n0 = nt * 8 + 2 * tig;
            *(float2*)&sd[m0 * SD + n0] = make_float2(acc[mt][nt][0], acc[mt][nt][1]);
            *(float2*)&sd[(m0 + 8) * SD + n0] = make_float2(acc[mt][nt][2], acc[mt][nt][3]);
        }
    }
    __syncthreads();

    {
        int pp = t >> 2, cq = t & 3;      // 64 px x 4 chunks
        int py = pp >> 3, px = pp & 7;
        int ph = ph0 + py, pw = pw0 + px;
        if (ph < 111 && pw < 111) {
            int mA = (2 * py) * 16 + 2 * px;
            bf16 oh[16], ol[16];
#pragma unroll
            for (int j = 0; j < 16; j++) {
                int col = cq * 16 + j;
                float v0 = sd[mA * SD + col];
                float v1 = sd[(mA + 1) * SD + col];
                float v2 = sd[(mA + 16) * SD + col];
                float v3 = sd[(mA + 17) * SD + col];
                float m = fmaxf(fmaxf(v0, v1), fmaxf(v2, v3));
                m += __ldg(&b1[co0 + col]);
                m = (m >= 0.f) ? m : LEAK * m;
                bf16 hh = __float2bfloat16(m);
                oh[j] = hh;
                ol[j] = __float2bfloat16(m - __bfloat162float(hh));
            }
            int chunkg = blockIdx.y * 4 + cq;
            size_t gi = ((((size_t)n * 8 + chunkg) * 111 + ph) * 111 + pw) * 16;
            *(uint4*)&outh[gi]     = *(const uint4*)&oh[0];
            *(uint4*)&outh[gi + 8] = *(const uint4*)&oh[8];
            *(uint4*)&outl[gi]     = *(const uint4*)&ol[0];
            *(uint4*)&outl[gi + 8] = *(const uint4*)&ol[8];
        }
    }
}

// ---------------------------------------------------------------------------
// Stages 2/3, tensor cores (verified R10 config). Implicit GEMM: block
// M = 128 conv positions (8 rows x 16 cols -> pooled 4x8), N = CO.
// 4 warps, ALL in M: warp tile M32 x N=CO. K = tap-loop x 16-ci chunks;
// bf16 hi+lo split. Triple-buffered cp.async staging, one barrier per
// chunk. B frags: one LDG.64 per n8-tile (frag-vec weight layout).
// OUTF=1: bf16 hi/lo chunk-last; OUTF=0: fp32 NCHW.
// ---------------------------------------------------------------------------
template<int CI, int CO, int HIN, int POUT, int OUTF>
__global__ __launch_bounds__(128)
void k_conv_mma(const bf16* __restrict__ inh, const bf16* __restrict__ inl,
                const bf16* __restrict__ wf,  const float* __restrict__ bg,
                bf16* __restrict__ outh, bf16* __restrict__ outl,
                float* __restrict__ outf)
{
    constexpr int NCH   = CI / 16;
    constexpr int NCHO  = CO / 16;
    constexpr int NT    = CO / 8;        // n8 tiles per warp (8 or 4)
    constexpr int NTX   = (POUT + 7) / 8;
    constexpr int SD    = CO + 4;
    constexpr int SLOT  = 24;            // ci-slot stride (conflict-free)
    constexpr int POS   = 10 * 18;       // tile positions incl. halo
    constexpr int SX_E  = POS * SLOT;    // elems per (buf, part)
    constexpr int BUF_E = 2 * SX_E;      // hi + lo

    extern __shared__ __align__(16) char smem_raw[];
    bf16* sbuf = (bf16*)smem_raw;        // 3 x BUF_E

    const int n   = blockIdx.z;
    const int ty  = blockIdx.x / NTX, tx = blockIdx.x % NTX;
    const int ph0 = ty * 4, pw0 = tx * 8;
    const int ih0 = 2 * ph0, iw0 = 2 * pw0;

    const int t    = threadIdx.x;
    const int lane = t & 31, wm = t >> 5;   // 4 warps, all in M
    const int g    = lane >> 2, tig = lane & 3;

    float acc[2][NT][4];
#pragma unroll
    for (int mt = 0; mt < 2; mt++)
#pragma unroll
        for (int nt = 0; nt < NT; nt++)
#pragma unroll
            for (int j = 0; j < 4; j++) acc[mt][nt][j] = 0.f;

    int abase[2];
#pragma unroll
    for (int mt = 0; mt < 2; mt++)
        abase[mt] = (((2 * wm + mt) * 18) + g) * SLOT + 2 * tig;

    // staging issue: chunk ch -> buffer b (cp.async, zfill halo)
    auto stage = [&](int ch, int b) {
        const bf16* srch = inh + ((size_t)(n * NCH + ch) * HIN * HIN) * 16;
        const bf16* srcl = inl + ((size_t)(n * NCH + ch) * HIN * HIN) * 16;
        bf16* dh = sbuf + b * BUF_E;
        bf16* dl = dh + SX_E;
        for (int u = t; u < POS * 2; u += 128) {
            int pos = u >> 1, h4 = u & 1;
            int r = pos / 18, c = pos - r * 18;
            int ir = ih0 + r, ic = iw0 + c;
            bool p = (ir < HIN) && (ic < HIN);
            size_t gi = ((size_t)ir * HIN + ic) * 16 + h4 * 8;
            int si = pos * SLOT + h4 * 8;
            cp16(dh + si, srch + gi, p);
            cp16(dl + si, srcl + gi, p);
        }
    };

    stage(0, 0);
    cp_commit();
    if (NCH > 1) { stage(1, 1); cp_commit(); }

    for (int ch = 0; ch < NCH; ch++) {
        if (ch + 1 < NCH) cp_wait<1>(); else cp_wait<0>();
        __syncthreads();

        if (ch + 2 < NCH) { stage(ch + 2, (ch + 2) % 3); cp_commit(); }

        const bf16* sx_hi = sbuf + (ch % 3) * BUF_E;
        const bf16* sx_lo = sx_hi + SX_E;
        const bf16* wfc   = wf + ((size_t)ch * CO) * 16;

#pragma unroll
        for (int kh = 0; kh < 3; kh++)
#pragma unroll
            for (int kw = 0; kw < 3; kw++) {
                const int tap  = kh * 3 + kw;
                const int toff = (kh * 18 + kw) * SLOT;

                unsigned b0[NT], b1[NT];
#pragma unroll
                for (int nt = 0; nt < NT; nt++) {
                    const bf16* wp = wfc + ((size_t)tap * NCH * CO +
                                            nt * 8 + g) * 16 + tig * 4;
                    uint2 bv = *(const uint2*)wp;
                    b0[nt] = bv.x;
                    b1[nt] = bv.y;
                }

#pragma unroll
                for (int mt = 0; mt < 2; mt++) {
                    int ai = abase[mt] + toff;
                    unsigned ah0 = *(const unsigned*)&sx_hi[ai];
                    unsigned ah2 = *(const unsigned*)&sx_hi[ai + 8];
                    unsigned ah1 = *(const unsigned*)&sx_hi[ai + 8 * SLOT];
                    unsigned ah3 = *(const unsigned*)&sx_hi[ai + 8 * SLOT + 8];
                    unsigned al0 = *(const unsigned*)&sx_lo[ai];
                    unsigned al2 = *(const unsigned*)&sx_lo[ai + 8];
                    unsigned al1 = *(const unsigned*)&sx_lo[ai + 8 * SLOT];
                    unsigned al3 = *(const unsigned*)&sx_lo[ai + 8 * SLOT + 8];
#pragma unroll
                    for (int nt = 0; nt < NT; nt++) {
                        mma_bf16(acc[mt][nt], ah0, ah1, ah2, ah3, b0[nt], b1[nt]);
                        mma_bf16(acc[mt][nt], al0, al1, al2, al3, b0[nt], b1[nt]);
                    }
                }
            }
    }
    __syncthreads();

    // ---- epilogue: fragments -> smem (overlay) ----
    float* sd = (float*)smem_raw;
#pragma unroll
    for (int mt = 0; mt < 2; mt++) {
        int m0 = wm * 32 + mt * 16 + g;
#pragma unroll
        for (int nt = 0; nt < NT; nt++) {
            int n0 = nt * 8 + 2 * tig;
            *(float2*)&sd[m0 * SD + n0] =
                make_float2(acc[mt][nt][0], acc[mt][nt][1]);
            *(float2*)&sd[(m0 + 8) * SD + n0] =
                make_float2(acc[mt][nt][2], acc[mt][nt][3]);
        }
    }
    __syncthreads();

    // ---- fused maxpool(2x2) + bias + leaky ----
    if (OUTF == 1) {
        // 32 pooled px x 4 chunks = 128 threads; 16 co per thread (NCHO==4)
        int pp = t >> 2, chunk = t & 3;
        int py = pp >> 3, px = pp & 7;
        int ph = ph0 + py, pw = pw0 + px;
        if (ph < POUT && pw < POUT) {
            int mA = (2 * py) * 16 + 2 * px;
            bf16 oh[16], ol[16];
#pragma unroll
            for (int j = 0; j < 16; j++) {
                int co = chunk * 16 + j;
                float v0 = sd[mA * SD + co];
                float v1 = sd[(mA + 1) * SD + co];
                float v2 = sd[(mA + 16) * SD + co];
                float v3 = sd[(mA + 17) * SD + co];
                float m = fmaxf(fmaxf(v0, v1), fmaxf(v2, v3));
                m += __ldg(&bg[co]);
                m = (m >= 0.f) ? m : LEAK * m;
                bf16 hh = __float2bfloat16(m);
                oh[j] = hh;
                ol[j] = __float2bfloat16(m - __bfloat162float(hh));
            }
            size_t gi = ((((size_t)n * NCHO + chunk) * POUT + ph) * POUT + pw) * 16;
            *(uint4*)&outh[gi]     = *(const uint4*)&oh[0];
            *(uint4*)&outh[gi + 8] = *(const uint4*)&oh[8];
            *(uint4*)&outl[gi]     = *(const uint4*)&ol[0];
            *(uint4*)&outl[gi + 8] = *(const uint4*)&ol[8];
        }
    } else {
        // fp32 NCHW output (feeds scalar conv4): 32 px x 4 co-groups of 8
        int pp = t >> 2, cq = t & 3;
        int py = pp >> 3, px = pp & 7;
        int ph = ph0 + py, pw = pw0 + px;
        if (ph < POUT && pw < POUT) {
            int mA = (2 * py) * 16 + 2 * px;
#pragma unroll
            for (int j = 0; j < 8; j++) {
                int co = cq * 8 + j;
                float v0 = sd[mA * SD + co];
                float v1 = sd[(mA + 1) * SD + co];
                float v2 = sd[(mA + 16) * SD + co];
                float v3 = sd[(mA + 17) * SD + co];
                float m = fmaxf(fmaxf(v0, v1), fmaxf(v2, v3));
                m += __ldg(&bg[co]);
                m = (m >= 0.f) ? m : LEAK * m;
                outf[(((size_t)n * CO + co) * POUT + ph) * POUT + pw] = m;
            }
        }
    }
}

// ---------------------------------------------------------------------------
// Stage 4: conv(32->8, kh=3 kw=2) + bias, no pool.
// ---------------------------------------------------------------------------
__global__ __launch_bounds__(256)
void k_conv4(const float* __restrict__ w4, const float* __restrict__ b4,
             float* __restrict__ out)
{
    __shared__ float sw[8][32][3][2];
    __shared__ float sb[8];
    const int t = threadIdx.x;
    for (int i = t; i < 8 * 32 * 6; i += 256)
        ((float*)sw)[i] = (w4[i] >= 0.f) ? 1.f : -1.f;
    if (t < 8) sb[t] = b4[t];
    __syncthreads();

    int idx = blockIdx.x * 256 + t;
    if (idx >= 32 * 8 * 24 * 25) return;
    int ow = idx % 25; int r = idx / 25;
    int oh = r % 24;   r /= 24;
    int co = r % 8;    int n = r / 8;

    const float* xn = g_buf3 + ((size_t)n * 32) * (26 * 26);
    float a = sb[co];
#pragma unroll 4
    for (int ci = 0; ci < 32; ci++) {
        const float* xr = xn + ci * 676 + oh * 26 + ow;
#pragma unroll
        for (int kh = 0; kh < 3; kh++)
#pragma unroll
            for (int kw = 0; kw < 2; kw++)
                a += sw[co][ci][kh][kw] * __ldg(&xr[kh * 26 + kw]);
    }
    out[idx] = a;
}

// ---------------------------------------------------------------------------
extern "C" void kernel_launch(void* const* d_in, const int* in_sizes, int n_in,
                              void* d_out, int out_size)
{
    (void)in_sizes; (void)n_in; (void)out_size;
    const float* x  = (const float*)d_in[0];
    const float* w1 = (const float*)d_in[1];
    const float* b1 = (const float*)d_in[2];
    const float* w2 = (const float*)d_in[3];
    const float* b2 = (const float*)d_in[4];
    const float* w3 = (const float*)d_in[5];
    const float* b3 = (const float*)d_in[6];
    const float* w4 = (const float*)d_in[7];
    const float* b4 = (const float*)d_in[8];
    float* out = (float*)d_out;

    bf16 *b1h, *b1l, *b2h, *b2l, *w2f, *w3f, *w1f;
    float* buf3;
    cudaGetSymbolAddress((void**)&b1h, g_b1h);
    cudaGetSymbolAddress((void**)&b1l, g_b1l);
    cudaGetSymbolAddress((void**)&b2h, g_b2h);
    cudaGetSymbolAddress((void**)&b2l, g_b2l);
    cudaGetSymbolAddress((void**)&w2f, g_w2f);
    cudaGetSymbolAddress((void**)&w3f, g_w3f);
    cudaGetSymbolAddress((void**)&w1f, g_w1f);
    cudaGetSymbolAddress((void**)&buf3, g_buf3);

    // conv2/3 smem: 3 staging buffers (3*2*4320*2B = 51840) >= epilogue
    const int smem23 = 3 * 2 * (10 * 18 * 24) * 2;  // 51840
    // conv1 smem: epilogue dominates (256 * 68 * 4 = 69632)
    const int smem1 = 256 * 68 * 4;
    cudaFuncSetAttribute(k_conv_mma<128, 64, 111, 54, 1>,
                         cudaFuncAttributeMaxDynamicSharedMemorySize, smem23);
    cudaFuncSetAttribute(k_conv_mma<64, 32, 54, 26, 0>,
                         cudaFuncAttributeMaxDynamicSharedMemorySize, smem23);
    cudaFuncSetAttribute(k_conv1_mma,
                         cudaFuncAttributeMaxDynamicSharedMemorySize, smem1);

    k_prep<<<dim3(368), 256>>>(w2, w3, w1);

    // conv1 (tensor): pooled 111 -> 14x14 tiles of pooled 8x8; 2 co halves
    k_conv1_mma<<<dim3(14 * 14, 2, 32), 256, smem1>>>(x, w1f, b1, b1h, b1l);

    // conv2: POUT=54 -> y tiles of 4 (14), x tiles of 8 (7)
    k_conv_mma<128, 64, 111, 54, 1><<<dim3(14 * 7, 1, 32), 128, smem23>>>(
        b1h, b1l, w2f, b2, b2h, b2l, nullptr);

    // conv3: POUT=26 -> y tiles 7, x tiles 4
    k_conv_mma<64, 32, 54, 26, 0><<<dim3(7 * 4, 1, 32), 128, smem23>>>(
        b2h, b2l, w3f, b3, nullptr, nullptr, buf3);

    k_conv4<<<dim3((32 * 8 * 24 * 25 + 255) / 256), 256>>>(w4, b4, out);
}